// round 8
// baseline (speedup 1.0000x reference)
#include <cuda_runtime.h>
#include <cuda_bf16.h>

#define TPAD   192
#define CCH    80
#define NSEG   7
#define SGRID  64
#define MINSEG 19
#define NV8    10              // 32-byte chunks per row (80 floats = 10 x 8)
#define ROWV8  (TPAD * NV8)    // 1920 chunks per batch
#define NTHR   512
#define NCTAS  444             // 148 SMs x 3 resident CTAs

// x is read-only and re-read across graph replays: keep it in L2.
// sm_103: eviction hints require 256-bit (.v4.b64) accesses.
__device__ __forceinline__ ulonglong4 ldg256_evict_last(const ulonglong4* p) {
    ulonglong4 v;
    asm volatile("ld.global.nc.L2::evict_last.v4.b64 {%0,%1,%2,%3}, [%4];"
                 : "=l"(v.x), "=l"(v.y), "=l"(v.z), "=l"(v.w) : "l"(p));
    return v;
}
// out is write-once, never re-read: don't let it pollute L2.
__device__ __forceinline__ void stg256_evict_first(ulonglong4* p, ulonglong4 v) {
    asm volatile("st.global.L2::evict_first.v4.b64 [%0], {%1,%2,%3,%4};"
                 :: "l"(p), "l"(v.x), "l"(v.y), "l"(v.z), "l"(v.w) : "memory");
}

__device__ __forceinline__ float2 u2f2(unsigned long long u) {
    float2 f;
    f.x = __uint_as_float((unsigned)(u & 0xffffffffull));
    f.y = __uint_as_float((unsigned)(u >> 32));
    return f;
}
__device__ __forceinline__ unsigned long long f22u(float2 f) {
    return (unsigned long long)__float_as_uint(f.x)
         | ((unsigned long long)__float_as_uint(f.y) << 32);
}
__device__ __forceinline__ unsigned long long lerp64(unsigned long long ua,
                                                     unsigned long long uc,
                                                     float lam) {
    const float2 a = u2f2(ua), c = u2f2(uc);
    float2 r;
    r.x = fmaf(lam, c.x - a.x, a.x);
    r.y = fmaf(lam, c.y - a.y, a.y);
    return f22u(r);
}

__global__ __launch_bounds__(NTHR, 3)
void interp_lnr_kernel(const float* __restrict__ x,
                       const int*   __restrict__ len_seq,
                       const float* __restrict__ scales,
                       const int*   __restrict__ len_seg_raw,
                       float*       __restrict__ out,
                       int B)
{
    const int tid = threadIdx.x;
    int b = blockIdx.x;
    if (b >= B) return;
    const int stride = gridDim.x;

    __shared__ float s_scale[NSEG];
    __shared__ int   s_lenseg[NSEG];
    __shared__ int   s_off[NSEG];
    __shared__ int   s_cnt[NSEG];
    __shared__ int   s_base[NSEG];
    __shared__ int   s_wcnt[14];       // 14 warps' popc over 448 slots
    __shared__ int   s_lseq;
    __shared__ int   s_src[TPAD];
    __shared__ float s_lam[TPAD];

    // Prefetch plan inputs for the first batch.
    float r_scale = 0.0f; int r_lenseg = 0; int r_lseq = 0;
    if (tid < NSEG) {
        r_scale  = scales[b * NSEG + tid] + 0.5f;
        r_lenseg = len_seg_raw[b * NSEG + tid] + MINSEG;
    }
    if (tid == 0) r_lseq = len_seq[b];

    while (true) {
        // Previous stream phase readers must be done before we rewrite tables.
        __syncthreads();

        // ---- Publish prefetched plan inputs; init tables ----
        if (tid < TPAD) { s_src[tid] = -1; s_lam[tid] = 0.0f; }
        if (tid < NSEG) { s_scale[tid] = r_scale; s_lenseg[tid] = r_lenseg; }
        if (tid == 0)   s_lseq = r_lseq;
        __syncthreads();

        // ---- Prefetch NEXT batch's plan inputs (latency hides under stream) ----
        const int bn = b + stride;
        if (bn < B) {
            if (tid < NSEG) {
                r_scale  = scales[bn * NSEG + tid] + 0.5f;
                r_lenseg = len_seg_raw[bn * NSEG + tid] + MINSEG;
            }
            if (tid == 0) r_lseq = len_seq[bn];
        }

        if (tid == 0) {
            int acc = 0;
            #pragma unroll
            for (int s = 0; s < NSEG; s++) { s_off[s] = acc; acc += s_lenseg[s]; }
        }
        __syncthreads();

        // Parallel mask evaluation: slot (s,i) for tid < 448; count via ballot.
        // Both mask terms are integer comparisons on exactly-representable floats.
        if (tid < NSEG * SGRID) {
            const int s = tid >> 6;
            const int i = tid & 63;
            const int lim = min(s_lenseg[s] - 1, s_lseq - 1 - s_off[s]);
            const float v = __fdiv_rn((float)i, s_scale[s]);  // IEEE RN, matches JAX
            const bool m = (lim > 0) && (floorf(v) < (float)lim);
            const unsigned bal = __ballot_sync(0xffffffffu, m);
            if ((tid & 31) == 0) s_wcnt[tid >> 5] = __popc(bal);
        }
        __syncthreads();

        if (tid == 0) {
            int acc = 0;
            #pragma unroll
            for (int s = 0; s < NSEG; s++) {
                const int cnt = s_wcnt[2 * s] + s_wcnt[2 * s + 1];
                s_base[s] = acc; s_cnt[s] = cnt; acc += cnt;
            }
        }
        __syncthreads();

        // Fill compact table (masked slots of a segment are a prefix of i).
        if (tid < NSEG * SGRID) {
            const int s = tid >> 6;
            const int i = tid & 63;
            if (i < s_cnt[s]) {
                const int p = s_base[s] + i;
                if (p < TPAD) {                  // pos >= 192 dropped by reference
                    const float v  = __fdiv_rn((float)i, s_scale[s]);
                    const float fl = floorf(v);
                    s_src[p] = min((int)fl + s_off[s], TPAD - 2);
                    s_lam[p] = v - fl;
                }
            }
        }
        __syncthreads();

        // ---- Stream phase: 1920 x 32B chunks, no syncs ----
        const ulonglong4* __restrict__ xb =
            (const ulonglong4*)(x + (size_t)b * TPAD * CCH);
        ulonglong4* __restrict__ ob =
            (ulonglong4*)(out + (size_t)b * TPAD * CCH);

        #pragma unroll
        for (int k = 0; k < 4; k++) {
            const int e = tid + k * NTHR;
            if (k < 3 || tid < ROWV8 - 3 * NTHR) {   // last pass: 384 active
                const int row = e / NV8;
                const int q   = e - row * NV8;
                const int   src = s_src[row];
                const float lam = s_lam[row];
                ulonglong4 r = make_ulonglong4(0ull, 0ull, 0ull, 0ull);
                if (src >= 0) {
                    const ulonglong4 a = ldg256_evict_last(&xb[src * NV8 + q]);
                    const ulonglong4 c = ldg256_evict_last(&xb[src * NV8 + NV8 + q]);
                    r.x = lerp64(a.x, c.x, lam);
                    r.y = lerp64(a.y, c.y, lam);
                    r.z = lerp64(a.z, c.z, lam);
                    r.w = lerp64(a.w, c.w, lam);
                }
                stg256_evict_first(&ob[e], r);
            }
        }

        if (bn >= B) break;
        b = bn;
    }
}

extern "C" void kernel_launch(void* const* d_in, const int* in_sizes, int n_in,
                              void* d_out, int out_size)
{
    const float* x           = (const float*)d_in[0];
    const int*   len_seq     = (const int*)  d_in[1];
    const float* scales      = (const float*)d_in[2];
    const int*   len_seg_raw = (const int*)  d_in[3];
    float*       out         = (float*)d_out;

    const int B    = in_sizes[1];
    const int grid = (B < NCTAS) ? B : NCTAS;
    interp_lnr_kernel<<<grid, NTHR>>>(x, len_seq, scales, len_seg_raw, out, B);
}

// round 9
// speedup vs baseline: 1.0327x; 1.0327x over previous
#include <cuda_runtime.h>
#include <cuda_bf16.h>

#define TPAD   192
#define CCH    80
#define NSEG   7
#define SGRID  64
#define MINSEG 19
#define NV8    10              // 32-byte chunks per row (80 floats = 10 x 8)
#define ROWV8  (TPAD * NV8)    // 1920 chunks per batch
#define NTHR   512

// x is read-only and re-read across graph replays: keep it in L2.
// sm_103: eviction hints require 256-bit (.v4.b64) accesses.
__device__ __forceinline__ ulonglong4 ldg256_evict_last(const ulonglong4* p) {
    ulonglong4 v;
    asm volatile("ld.global.nc.L2::evict_last.v4.b64 {%0,%1,%2,%3}, [%4];"
                 : "=l"(v.x), "=l"(v.y), "=l"(v.z), "=l"(v.w) : "l"(p));
    return v;
}
// out is write-once, never re-read: don't let it pollute L2.
__device__ __forceinline__ void stg256_evict_first(ulonglong4* p, ulonglong4 v) {
    asm volatile("st.global.L2::evict_first.v4.b64 [%0], {%1,%2,%3,%4};"
                 :: "l"(p), "l"(v.x), "l"(v.y), "l"(v.z), "l"(v.w) : "memory");
}

__device__ __forceinline__ float2 u2f2(unsigned long long u) {
    float2 f;
    f.x = __uint_as_float((unsigned)(u & 0xffffffffull));
    f.y = __uint_as_float((unsigned)(u >> 32));
    return f;
}
__device__ __forceinline__ unsigned long long f22u(float2 f) {
    return (unsigned long long)__float_as_uint(f.x)
         | ((unsigned long long)__float_as_uint(f.y) << 32);
}
__device__ __forceinline__ unsigned long long lerp64(unsigned long long ua,
                                                     unsigned long long uc,
                                                     float lam) {
    const float2 a = u2f2(ua), c = u2f2(uc);
    float2 r;
    r.x = fmaf(lam, c.x - a.x, a.x);
    r.y = fmaf(lam, c.y - a.y, a.y);
    return f22u(r);
}

__global__ __launch_bounds__(NTHR, 4)
void interp_lnr_kernel(const float* __restrict__ x,
                       const int*   __restrict__ len_seq,
                       const float* __restrict__ scales,
                       const int*   __restrict__ len_seg_raw,
                       float*       __restrict__ out)
{
    const int b   = blockIdx.x;
    const int tid = threadIdx.x;

    __shared__ float s_scale[NSEG];
    __shared__ int   s_lenseg[NSEG];
    __shared__ int   s_off[NSEG];
    __shared__ int   s_cnt[NSEG];
    __shared__ int   s_base[NSEG];
    __shared__ int   s_wcnt[14];       // 14 warps cover 448 slots
    __shared__ int   s_src[TPAD];
    __shared__ float s_lam[TPAD];

    // Pre-fill: pad rows get src = -1, lam = 0 (overwritten for live rows).
    if (tid < TPAD) { s_src[tid] = -1; s_lam[tid] = 0.0f; }

    if (tid < NSEG) {
        s_scale[tid]  = scales[b * NSEG + tid] + 0.5f;
        s_lenseg[tid] = len_seg_raw[b * NSEG + tid] + MINSEG;
    }
    __syncthreads();

    if (tid == 0) {
        int acc = 0;
        #pragma unroll
        for (int s = 0; s < NSEG; s++) { s_off[s] = acc; acc += s_lenseg[s]; }
    }
    __syncthreads();

    // Parallel mask evaluation: slot (s,i) for tid < 448; count via ballot.
    // Both mask terms are integer comparisons on exactly-representable floats.
    if (tid < NSEG * SGRID) {
        const int s = tid >> 6;
        const int i = tid & 63;
        const int lim = min(s_lenseg[s] - 1, len_seq[b] - 1 - s_off[s]);
        const float v = __fdiv_rn((float)i, s_scale[s]);   // IEEE RN, matches JAX
        const bool m = (lim > 0) && (floorf(v) < (float)lim);
        const unsigned bal = __ballot_sync(0xffffffffu, m);
        if ((tid & 31) == 0) s_wcnt[tid >> 5] = __popc(bal);
    }
    __syncthreads();

    if (tid == 0) {
        int acc = 0;
        #pragma unroll
        for (int s = 0; s < NSEG; s++) {
            const int cnt = s_wcnt[2 * s] + s_wcnt[2 * s + 1];
            s_base[s] = acc; s_cnt[s] = cnt; acc += cnt;
        }
    }
    __syncthreads();

    // Fill compact table (masked slots of a segment are a prefix of i).
    if (tid < NSEG * SGRID) {
        const int s = tid >> 6;
        const int i = tid & 63;
        if (i < s_cnt[s]) {
            const int p = s_base[s] + i;
            if (p < TPAD) {                      // pos >= 192 dropped by reference
                const float v  = __fdiv_rn((float)i, s_scale[s]);
                const float fl = floorf(v);
                s_src[p] = min((int)fl + s_off[s], TPAD - 2);
                s_lam[p] = v - fl;
            }
        }
    }
    __syncthreads();

    const ulonglong4* __restrict__ xb =
        (const ulonglong4*)(x + (size_t)b * TPAD * CCH);
    ulonglong4* __restrict__ ob =
        (ulonglong4*)(out + (size_t)b * TPAD * CCH);

    // Stream 1920 x 32B chunks. REVERSE macro order: the high-row tail is
    // mostly zero rows (no load dependency), so issuing it first fills the
    // DRAM write pipe immediately while the gather loads of the live rows
    // are still in flight.
    #pragma unroll
    for (int k = 3; k >= 0; k--) {
        const int e = tid + k * NTHR;
        if (k < 3 || tid < ROWV8 - 3 * NTHR) {   // k==3: only 384 active
            const int row = e / NV8;
            const int q   = e - row * NV8;
            const int   src = s_src[row];
            const float lam = s_lam[row];
            ulonglong4 r = make_ulonglong4(0ull, 0ull, 0ull, 0ull);
            if (src >= 0) {
                const ulonglong4 a = ldg256_evict_last(&xb[src * NV8 + q]);
                const ulonglong4 c = ldg256_evict_last(&xb[src * NV8 + NV8 + q]);
                r.x = lerp64(a.x, c.x, lam);
                r.y = lerp64(a.y, c.y, lam);
                r.z = lerp64(a.z, c.z, lam);
                r.w = lerp64(a.w, c.w, lam);
            }
            stg256_evict_first(&ob[e], r);
        }
    }
}

extern "C" void kernel_launch(void* const* d_in, const int* in_sizes, int n_in,
                              void* d_out, int out_size)
{
    const float* x           = (const float*)d_in[0];
    const int*   len_seq     = (const int*)  d_in[1];
    const float* scales      = (const float*)d_in[2];
    const int*   len_seg_raw = (const int*)  d_in[3];
    float*       out         = (float*)d_out;

    const int B = in_sizes[1];
    interp_lnr_kernel<<<B, NTHR>>>(x, len_seq, scales, len_seg_raw, out);
}

// round 12
// speedup vs baseline: 1.0710x; 1.0370x over previous
#include <cuda_runtime.h>
#include <cuda_bf16.h>

#define TPAD   192
#define CCH    80
#define NSEG   7
#define SGRID  64
#define MINSEG 19
#define NV8    10              // 32-byte chunks per row (80 floats = 10 x 8)
#define ROWV8  (TPAD * NV8)    // 1920 chunks per batch
#define NTHR   512

typedef unsigned long long u64;

// x is read-only and re-read across graph replays: keep it in L2.
// sm_103: eviction hints require 256-bit (.v4.b64) accesses.
__device__ __forceinline__ void ldg256_evict_last(const void* p, u64 v[4]) {
    asm volatile("ld.global.nc.L2::evict_last.v4.b64 {%0,%1,%2,%3}, [%4];"
                 : "=l"(v[0]), "=l"(v[1]), "=l"(v[2]), "=l"(v[3]) : "l"(p));
}
// out is write-once, never re-read: don't let it pollute L2.
__device__ __forceinline__ void stg256_evict_first(void* p, const u64 v[4]) {
    asm volatile("st.global.L2::evict_first.v4.b64 [%0], {%1,%2,%3,%4};"
                 :: "l"(p), "l"(v[0]), "l"(v[1]), "l"(v[2]), "l"(v[3]) : "memory");
}
// Register-free read-ahead into L2 (decouples read stream from store stream).
__device__ __forceinline__ void prefetch_l2(const void* p) {
    asm volatile("prefetch.global.L2 [%0];" :: "l"(p));
}

__device__ __forceinline__ float2 u2f2(u64 u) {
    float2 f;
    f.x = __uint_as_float((unsigned)(u & 0xffffffffull));
    f.y = __uint_as_float((unsigned)(u >> 32));
    return f;
}
__device__ __forceinline__ u64 f22u(float2 f) {
    return (u64)__float_as_uint(f.x) | ((u64)__float_as_uint(f.y) << 32);
}
__device__ __forceinline__ u64 lerp64(u64 ua, u64 uc, float lam) {
    const float2 a = u2f2(ua), c = u2f2(uc);
    float2 r;
    r.x = fmaf(lam, c.x - a.x, a.x);
    r.y = fmaf(lam, c.y - a.y, a.y);
    return f22u(r);
}

__global__ __launch_bounds__(NTHR)
void interp_lnr_kernel(const float* __restrict__ x,
                       const int*   __restrict__ len_seq,
                       const float* __restrict__ scales,
                       const int*   __restrict__ len_seg_raw,
                       float*       __restrict__ out)
{
    const int b   = blockIdx.x;
    const int tid = threadIdx.x;

    __shared__ float s_scale[NSEG];
    __shared__ int   s_lenseg[NSEG];
    __shared__ int   s_off[NSEG];
    __shared__ int   s_cnt[NSEG];
    __shared__ int   s_base[NSEG];
    __shared__ int   s_wcnt[14];       // 14 warps cover 448 slots
    __shared__ int   s_src[TPAD];
    __shared__ float s_lam[TPAD];

    // Pre-fill: pad rows get src = -1, lam = 0 (overwritten for live rows).
    if (tid < TPAD) { s_src[tid] = -1; s_lam[tid] = 0.0f; }

    if (tid < NSEG) {
        s_scale[tid]  = scales[b * NSEG + tid] + 0.5f;
        s_lenseg[tid] = len_seg_raw[b * NSEG + tid] + MINSEG;
    }
    __syncthreads();

    if (tid == 0) {
        int acc = 0;
        #pragma unroll
        for (int s = 0; s < NSEG; s++) { s_off[s] = acc; acc += s_lenseg[s]; }
    }
    __syncthreads();

    // Parallel mask evaluation: slot (s,i) for tid < 448; count via ballot.
    // Both mask terms are integer comparisons on exactly-representable floats.
    if (tid < NSEG * SGRID) {
        const int s = tid >> 6;
        const int i = tid & 63;
        const int lim = min(s_lenseg[s] - 1, len_seq[b] - 1 - s_off[s]);
        const float v = __fdiv_rn((float)i, s_scale[s]);   // IEEE RN, matches JAX
        const bool m = (lim > 0) && (floorf(v) < (float)lim);
        const unsigned bal = __ballot_sync(0xffffffffu, m);
        if ((tid & 31) == 0) s_wcnt[tid >> 5] = __popc(bal);
    }
    __syncthreads();

    if (tid == 0) {
        int acc = 0;
        #pragma unroll
        for (int s = 0; s < NSEG; s++) {
            const int cnt = s_wcnt[2 * s] + s_wcnt[2 * s + 1];
            s_base[s] = acc; s_cnt[s] = cnt; acc += cnt;
        }
    }
    __syncthreads();

    // Fill compact table (masked slots of a segment are a prefix of i).
    if (tid < NSEG * SGRID) {
        const int s = tid >> 6;
        const int i = tid & 63;
        if (i < s_cnt[s]) {
            const int p = s_base[s] + i;
            if (p < TPAD) {                      // pos >= 192 dropped by reference
                const float v  = __fdiv_rn((float)i, s_scale[s]);
                const float fl = floorf(v);
                s_src[p] = min((int)fl + s_off[s], TPAD - 2);
                s_lam[p] = v - fl;
            }
        }
    }
    __syncthreads();

    const char* __restrict__ xb = (const char*)(x   + (size_t)b * TPAD * CCH);
    char*       __restrict__ ob = (char*)      (out + (size_t)b * TPAD * CCH);

    // ---- Prefetch burst: pull this batch's entire gather set into L2,
    //      register-free, before the load->fma->store chain starts. ----
    #pragma unroll
    for (int k = 0; k < 4; k++) {
        const int e = tid + k * NTHR;
        if (k < 3 || tid < ROWV8 - 3 * NTHR) {
            const int row = e / NV8;
            const int q   = e - row * NV8;
            const int src = s_src[row];
            if (src >= 0) {
                prefetch_l2(xb + (size_t)(src * NV8 + q) * 32);
                prefetch_l2(xb + (size_t)(src * NV8 + NV8 + q) * 32);
            }
        }
    }

    // ---- Stream 1920 x 32B chunks with 256-bit accesses ----
    for (int e = tid; e < ROWV8; e += NTHR) {
        const int row = e / NV8;
        const int q   = e - row * NV8;
        const int   src = s_src[row];
        const float lam = s_lam[row];
        u64 r[4] = {0ull, 0ull, 0ull, 0ull};
        if (src >= 0) {
            u64 a[4], c[4];
            ldg256_evict_last(xb + (size_t)(src * NV8 + q) * 32, a);
            ldg256_evict_last(xb + (size_t)(src * NV8 + NV8 + q) * 32, c);
            r[0] = lerp64(a[0], c[0], lam);
            r[1] = lerp64(a[1], c[1], lam);
            r[2] = lerp64(a[2], c[2], lam);
            r[3] = lerp64(a[3], c[3], lam);
        }
        stg256_evict_first(ob + (size_t)e * 32, r);
    }
}

extern "C" void kernel_launch(void* const* d_in, const int* in_sizes, int n_in,
                              void* d_out, int out_size)
{
    const float* x           = (const float*)d_in[0];
    const int*   len_seq     = (const int*)  d_in[1];
    const float* scales      = (const float*)d_in[2];
    const int*   len_seg_raw = (const int*)  d_in[3];
    float*       out         = (float*)d_out;

    const int B = in_sizes[1];
    interp_lnr_kernel<<<B, NTHR>>>(x, len_seq, scales, len_seg_raw, out);
}